// round 12
// baseline (speedup 1.0000x reference)
#include <cuda_runtime.h>
#include <cuda_bf16.h>
#include <cuda_fp16.h>
#include <math.h>

// Problem constants
#define B_  2
#define C_  192       // DINNER
#define Hh  48
#define Ww  48
#define L_  2304      // H*W
#define K_  4
#define N_  16
#define R_  12
#define D44 44        // R + 2N
#define KC  (K_*C_)   // 768

#define NCHUNK 6
#define GPC    24     // groups of 16 per chunk (chunk = 384)
#define NBX    192    // blocks per chunk (x-dim), 4 warps each
#define LOG2E  1.4426950408889634f

// BC layout (fp16): per (b,k), per group g (16 positions):
//   B block: [t:4][n:16][4 halfs] (512B) then C block likewise (512B)
// record stride = 512 halfs.

// ---------------- scratch (device globals; no allocation allowed) ------------
__device__ float  g_xT[B_ * C_ * L_];
__device__ __half g_BC[B_ * K_ * (L_ / 16) * 512];
__device__ float  g_SP[B_ * K_ * C_ * L_];
__device__ float  g_Y [B_ * K_ * C_ * L_];
__device__ float  g_HP [KC * B_ * NCHUNK * N_];   // chunk-local h_end  [ch][s][n]
__device__ float  g_PP [KC * B_ * NCHUNK * N_];   // chunk decay prod   [ch][s][n]
__device__ int    g_FLAG[NCHUNK * NBX];           // look-back flags

// ---------------- kernel 1: transpose x -> xT (+ zero flags) -----------------
__global__ void k_transpose(const float* __restrict__ x) {
    if (blockIdx.x == 0)
        for (int i = threadIdx.x; i < NCHUNK * NBX; i += blockDim.x)
            g_FLAG[i] = 0;
    int bc = blockIdx.x;
    __shared__ float s[L_];
    float4* s4 = reinterpret_cast<float4*>(s);
    const float4* src = reinterpret_cast<const float4*>(x + (size_t)bc * L_);
    for (int i = threadIdx.x; i < L_ / 4; i += blockDim.x) s4[i] = src[i];
    __syncthreads();
    float4* dst = reinterpret_cast<float4*>(g_xT + (size_t)bc * L_);
    for (int i = threadIdx.x; i < L_ / 4; i += blockDim.x) {
        int p = 4 * i;                 // dst index j = w*Hh + h
        int w = p / Hh, h = p % Hh;    // 4 consecutive j -> same w, h..h+3
        dst[i] = make_float4(s[(h + 0) * Ww + w], s[(h + 1) * Ww + w],
                             s[(h + 2) * Ww + w], s[(h + 3) * Ww + w]);
    }
}

// ---------------- kernel 2: proj GEMM + BC repack + dt-proj + softplus --------
// P-tile = 32 positions. grid (72, 1, 4).
__global__ __launch_bounds__(256) void k_proj(
    const float* __restrict__ x,
    const float* __restrict__ Wp,        // [K*44][192]
    const float* __restrict__ dtw,       // [K][C][R]
    const float* __restrict__ dt_bias)   // [K*C]
{
    int bs = blockIdx.z;            // b*2 + s
    int b  = bs >> 1, s = bs & 1;
    int p0 = blockIdx.x * 32;

    const float* X = (s ? g_xT : x) + (size_t)b * C_ * L_;

    __shared__ float Ws[16][96];        // [kk][m]
    __shared__ float Xs[16][32];        // [kk][pp]
    __shared__ float dtw2[2][C_ * R_];  // per k-part, [c*12 + r]
    __shared__ float dts2[2][R_][32];   // staged dt rows

    int tid = threadIdx.x;
    int tx = tid & 15, ty = tid >> 4;

    // load dt weights for both k-parts (k = s, s+2)
    for (int part = 0; part < 2; part++) {
        int k = s + 2 * part;
        for (int idx = tid; idx < C_ * R_; idx += 256)
            dtw2[part][idx] = dtw[(size_t)k * C_ * R_ + idx];
    }

    float acc[6][2];
#pragma unroll
    for (int i = 0; i < 6; i++) { acc[i][0] = 0.f; acc[i][1] = 0.f; }

    for (int c0 = 0; c0 < C_; c0 += 16) {
        for (int idx = tid; idx < 96 * 16; idx += 256) {
            int m = idx >> 4, kk = idx & 15;
            float v = 0.f;
            if (m < 88) {
                int k = s + (m < D44 ? 0 : 2);
                int d = (m < D44) ? m : (m - D44);
                v = Wp[(size_t)(k * D44 + d) * C_ + c0 + kk];
            }
            Ws[kk][m] = v;
        }
        for (int idx = tid; idx < 16 * 32; idx += 256) {
            int c = idx >> 5, pp = idx & 31;
            Xs[c][pp] = X[(size_t)(c0 + c) * L_ + p0 + pp];
        }
        __syncthreads();
#pragma unroll
        for (int kk = 0; kk < 16; kk++) {
            float xa0 = Xs[kk][tx], xa1 = Xs[kk][tx + 16];
            float wa[6];
#pragma unroll
            for (int i = 0; i < 6; i++) wa[i] = Ws[kk][ty + 16 * i];
#pragma unroll
            for (int i = 0; i < 6; i++) {
                acc[i][0] = fmaf(wa[i], xa0, acc[i][0]);
                acc[i][1] = fmaf(wa[i], xa1, acc[i][1]);
            }
        }
        __syncthreads();
    }

    // epilogue: dt rows -> smem; B/C rows -> fp16 global layout
#pragma unroll
    for (int i = 0; i < 6; i++) {
        int m = ty + 16 * i;
        if (m < 88) {
            int part = (m < D44) ? 0 : 1;
            int d = m - part * D44;
            int k = s + 2 * part;
            if (d < R_) {
                dts2[part][d][tx]      = acc[i][0];
                dts2[part][d][tx + 16] = acc[i][1];
            } else {
                int jbc = d - R_;
                int n = jbc & 15, isC = jbc >> 4;
                __half* base = g_BC + (size_t)(b * K_ + k) * (L_ / 16) * 512;
#pragma unroll
                for (int j = 0; j < 2; j++) {
                    int p = p0 + tx + 16 * j;
                    int g = p >> 4, t = (p >> 2) & 3, e = p & 3;
                    base[(size_t)g * 512 + isC * 256 + t * 64 + n * 4 + e] =
                        __float2half(acc[i][j]);
                }
            }
        }
    }
    __syncthreads();

    // dt projection + softplus for both k-parts: 2 * 192 * 32 outputs
    for (int idx = tid; idx < 2 * C_ * 32; idx += 256) {
        int part = idx / (C_ * 32);
        int rem  = idx - part * (C_ * 32);
        int c = rem >> 5, p = rem & 31;
        int k = s + 2 * part;
        float accv = dt_bias[k * C_ + c];
        const float* wr = &dtw2[part][c * R_];
#pragma unroll
        for (int r = 0; r < R_; r++)
            accv = fmaf(wr[r], dts2[part][r][p], accv);
        float sp = (accv > 20.f) ? accv : log1pf(__expf(accv));
        g_SP[(size_t)((b * K_ + k) * C_ + c) * L_ + p0 + p] = sp;
    }
}

// half4 load helper: one LDG.64, expand to 4 floats
__device__ __forceinline__ void ld_half4(const __half* p, float* out) {
    uint2 raw = *reinterpret_cast<const uint2*>(p);
    __half2 h0 = *reinterpret_cast<__half2*>(&raw.x);
    __half2 h1 = *reinterpret_cast<__half2*>(&raw.y);
    float2 f0 = __half22float2(h0), f1 = __half22float2(h1);
    out[0] = f0.x; out[1] = f0.y; out[2] = f1.x; out[3] = f1.y;
}

// ---------------- scan phase A body: chunk-local (h_end, P) -------------------
template<bool FWD>
__device__ __forceinline__ void scan_pA(
    const float* __restrict__ sp, const float* __restrict__ u,
    const __half* __restrict__ bc, float a2, int n, int g0,
    float& h, float& P)
{
    h = 0.f;
    float ssum = 0.f;
    for (int g = g0; g < g0 + GPC; g++) {
        int q = FWD ? 16 * g : (L_ - 16 - 16 * g);
        const __half* rec = bc + (size_t)(q >> 4) * 512 + n * 4;
        float spArr[16], uArr[16], Bl[16];
#pragma unroll
        for (int t = 0; t < 4; t++) {
            float4 s4 = *reinterpret_cast<const float4*>(sp + q + 4 * t);
            float4 u4 = *reinterpret_cast<const float4*>(u  + q + 4 * t);
            ld_half4(rec + t * 64, Bl + 4 * t);
            spArr[4*t+0]=s4.x; spArr[4*t+1]=s4.y; spArr[4*t+2]=s4.z; spArr[4*t+3]=s4.w;
            uArr [4*t+0]=u4.x; uArr [4*t+1]=u4.y; uArr [4*t+2]=u4.z; uArr [4*t+3]=u4.w;
        }
        float dA[16], dBu[16];
#pragma unroll
        for (int j = 0; j < 16; j++) {
            int mj = FWD ? j : 15 - j;
            float s_ = spArr[mj];
            ssum += s_;
            dA[j]  = exp2f(s_ * a2);
            dBu[j] = s_ * uArr[mj] * Bl[mj];
        }
#pragma unroll
        for (int j = 0; j < 16; j++)
            h = fmaf(dA[j], h, dBu[j]);
    }
    P = exp2f(a2 * ssum);
}

// ---------------- scan phase B body: full scan + reduction --------------------
template<bool FWD>
__device__ __forceinline__ void scan_pB(
    const float* __restrict__ sp, const float* __restrict__ u,
    const __half* __restrict__ bc, float* __restrict__ y,
    float a2, float Dv, int n, int g0, float h)
{
    const unsigned FULL = 0xffffffffu;
    const bool hi8 = (n & 8), hi4 = (n & 4), hi2 = (n & 2), hi1 = (n & 1);

    for (int g = g0; g < g0 + GPC; g++) {
        int q = FWD ? 16 * g : (L_ - 16 - 16 * g);
        const __half* rec = bc + (size_t)(q >> 4) * 512 + n * 4;

        float spArr[16], uArr[16], Bl[16], Cl[16];
#pragma unroll
        for (int t = 0; t < 4; t++) {
            float4 s4 = *reinterpret_cast<const float4*>(sp + q + 4 * t);
            float4 u4 = *reinterpret_cast<const float4*>(u  + q + 4 * t);
            ld_half4(rec + t * 64, Bl + 4 * t);
            ld_half4(rec + 256 + t * 64, Cl + 4 * t);
            spArr[4*t+0]=s4.x; spArr[4*t+1]=s4.y; spArr[4*t+2]=s4.z; spArr[4*t+3]=s4.w;
            uArr [4*t+0]=u4.x; uArr [4*t+1]=u4.y; uArr [4*t+2]=u4.z; uArr [4*t+3]=u4.w;
        }

        float dA[16], dBu[16];
#pragma unroll
        for (int j = 0; j < 16; j++) {
            int mj = FWD ? j : 15 - j;
            float s_ = spArr[mj];
            dA[j]  = exp2f(s_ * a2);
            dBu[j] = s_ * uArr[mj] * Bl[mj];
        }

        float yp[16];
#pragma unroll
        for (int j = 0; j < 16; j++) {
            int mj = FWD ? j : 15 - j;
            h = fmaf(dA[j], h, dBu[j]);
            yp[j] = h * Cl[mj];
        }

        float w8[8];
#pragma unroll
        for (int t = 0; t < 8; t++) {
            float keepv = hi8 ? yp[t + 8] : yp[t];
            float sendv = hi8 ? yp[t] : yp[t + 8];
            w8[t] = keepv + __shfl_xor_sync(FULL, sendv, 8);
        }
        float w4[4];
#pragma unroll
        for (int t = 0; t < 4; t++) {
            float keepv = hi4 ? w8[t + 4] : w8[t];
            float sendv = hi4 ? w8[t] : w8[t + 4];
            w4[t] = keepv + __shfl_xor_sync(FULL, sendv, 4);
        }
        float w2[2];
#pragma unroll
        for (int t = 0; t < 2; t++) {
            float keepv = hi2 ? w4[t + 2] : w4[t];
            float sendv = hi2 ? w4[t] : w4[t + 2];
            w2[t] = keepv + __shfl_xor_sync(FULL, sendv, 2);
        }
        {
            float keepv = hi1 ? w2[1] : w2[0];
            float sendv = hi1 ? w2[0] : w2[1];
            float yred = keepv + __shfl_xor_sync(FULL, sendv, 1);
            int p = q + (FWD ? n : 15 - n);
            y[p] = fmaf(Dv, u[p], yred);
        }
    }
}

// ---------------- fused single-pass scan with decoupled look-back -------------
__global__ __launch_bounds__(128) void k_scanf(
    const float* __restrict__ x,
    const float* __restrict__ A_logs,
    const float* __restrict__ Ds)
{
    int warpId = threadIdx.x >> 5;          // 0..3
    int lane = threadIdx.x & 31;
    int bx = blockIdx.x;
    int gw = bx * 4 + warpId;               // 0..767
    int s = blockIdx.y;                      // chunk (scan-time)
    int half = lane >> 4, n = lane & 15;
    int ch = gw * 2 + half;                  // 0..1535
    int c = ch % C_;
    int k = (ch / C_) & 3;
    int b = ch / (K_ * C_);
    int kc = k * C_ + c;

    float a2 = -LOG2E * __expf(A_logs[kc * N_ + n]);
    float Dv = Ds[kc];

    const float* sp = g_SP + (size_t)ch * L_;
    const float* u  = ((k & 1) ? g_xT : x) + (size_t)(b * C_ + c) * L_;
    const __half* bc = g_BC + (size_t)(b * K_ + k) * (L_ / 16) * 512;
    float* y        = g_Y + (size_t)ch * L_;

    bool fwd = (k < 2);

    // ---- phase A: local (h,P); skipped for last chunk (unused) ----
    if (s < NCHUNK - 1) {
        float h, P;
        if (fwd) scan_pA<true >(sp, u, bc, a2, n, s * GPC, h, P);
        else     scan_pA<false>(sp, u, bc, a2, n, s * GPC, h, P);
        size_t o = ((size_t)ch * NCHUNK + s) * N_ + n;
        g_HP[o] = h;
        g_PP[o] = P;
        __syncthreads();
        if (threadIdx.x == 0) {
            __threadfence();
            atomicExch(&g_FLAG[s * NBX + bx], 1);
        }
    }

    // ---- look-back: wait for all predecessor chunks, fold h0 ----
    float h0 = 0.f;
    if (s > 0) {
        if (threadIdx.x < s) {
            while (atomicAdd(&g_FLAG[threadIdx.x * NBX + bx], 0) == 0)
                __nanosleep(64);
            __threadfence();
        }
        __syncthreads();

        float Pv[NCHUNK - 1], Hv[NCHUNK - 1];
#pragma unroll
        for (int s2 = 0; s2 < NCHUNK - 1; s2++) {
            size_t o = ((size_t)ch * NCHUNK + s2) * N_ + n;
            bool act = (s2 < s);
            Pv[s2] = act ? __ldcg(&g_PP[o]) : 1.f;
            Hv[s2] = act ? __ldcg(&g_HP[o]) : 0.f;
        }
#pragma unroll
        for (int s2 = 0; s2 < NCHUNK - 1; s2++)
            h0 = fmaf(Pv[s2], h0, Hv[s2]);
    }

    // ---- phase B: full scan with corrected h0 ----
    if (fwd) scan_pB<true >(sp, u, bc, y, a2, Dv, n, s * GPC, h0);
    else     scan_pB<false>(sp, u, bc, y, a2, Dv, n, s * GPC, h0);
}

// ---------------- kernel 4: cross merge (vectorized, full-MLP) ----------------
__global__ __launch_bounds__(256) void k_merge(float* __restrict__ out) {
    int bc = blockIdx.x;
    int b = bc / C_, c = bc % C_;
    const float4* y0 = reinterpret_cast<const float4*>(g_Y + (size_t)((b * K_ + 0) * C_ + c) * L_);
    const float4* y1 = reinterpret_cast<const float4*>(g_Y + (size_t)((b * K_ + 1) * C_ + c) * L_);
    const float4* y2 = reinterpret_cast<const float4*>(g_Y + (size_t)((b * K_ + 2) * C_ + c) * L_);
    const float4* y3 = reinterpret_cast<const float4*>(g_Y + (size_t)((b * K_ + 3) * C_ + c) * L_);
    __shared__ float s1[L_];
    float4* s1v = reinterpret_cast<float4*>(s1);

    int tid = threadIdx.x;
    float4 r02[3];
#pragma unroll
    for (int t = 0; t < 3; t++) {
        int i = tid + 256 * t;
        if (i < L_ / 4) {
            float4 a = y1[i], bb = y3[i];
            s1v[i] = make_float4(a.x + bb.x, a.y + bb.y, a.z + bb.z, a.w + bb.w);
            float4 p = y0[i], q = y2[i];
            r02[t] = make_float4(p.x + q.x, p.y + q.y, p.z + q.z, p.w + q.w);
        }
    }
    __syncthreads();

    float4* o4 = reinterpret_cast<float4*>(out + (size_t)bc * L_);
#pragma unroll
    for (int t = 0; t < 3; t++) {
        int i = tid + 256 * t;
        if (i < L_ / 4) {
            int p = 4 * i;               // out index j = h*Ww + w
            int h = p / Ww, w = p % Ww;  // 4 consecutive j -> same h, w..w+3
            float4 v = r02[t];
            v.x += s1[(w + 0) * Hh + h];
            v.y += s1[(w + 1) * Hh + h];
            v.z += s1[(w + 2) * Hh + h];
            v.w += s1[(w + 3) * Hh + h];
            o4[i] = v;
        }
    }
}

// ---------------- launch -------------------------------------------------------
extern "C" void kernel_launch(void* const* d_in, const int* in_sizes, int n_in,
                              void* d_out, int out_size) {
    const float* x       = (const float*)d_in[0];
    const float* xpw     = (const float*)d_in[1];
    const float* dtw     = (const float*)d_in[2];
    const float* A_logs  = (const float*)d_in[3];
    const float* Ds      = (const float*)d_in[4];
    const float* dt_bias = (const float*)d_in[5];
    float* out = (float*)d_out;

    k_transpose<<<B_ * C_, 256>>>(x);

    {
        dim3 grid(L_ / 32, 1, 4);
        k_proj<<<grid, 256>>>(x, xpw, dtw, dt_bias);
    }
    {
        dim3 grid(NBX, NCHUNK);
        k_scanf<<<grid, 128>>>(x, A_logs, Ds);
    }
    k_merge<<<B_ * C_, 256>>>(out);
}

// round 13
// speedup vs baseline: 1.0026x; 1.0026x over previous
#include <cuda_runtime.h>
#include <cuda_bf16.h>
#include <cuda_fp16.h>
#include <math.h>

// Problem constants
#define B_  2
#define C_  192       // DINNER
#define Hh  48
#define Ww  48
#define L_  2304      // H*W
#define K_  4
#define N_  16
#define R_  12
#define D44 44        // R + 2N
#define KC  (K_*C_)   // 768

#define NCHUNK 16
#define BPC    18     // 8-position batches per chunk (chunk = 144)
#define NBX    192    // blocks per chunk (x-dim), 4 warps each
#define LOG2E  1.4426950408889634f

// BC layout (fp16): per (b,k), per 16-position record g:
//   B block: [t:4][n:16][4 halfs] (512B) then C block likewise (512B)
// record stride = 512 halfs.

// ---------------- scratch (device globals; no allocation allowed) ------------
__device__ float  g_xT[B_ * C_ * L_];
__device__ __half g_BC[B_ * K_ * (L_ / 16) * 512];
__device__ float  g_SP[B_ * K_ * C_ * L_];
__device__ float  g_Y [B_ * K_ * C_ * L_];
__device__ float  g_HP [KC * B_ * NCHUNK * N_];   // chunk-local h_end  [ch][s][n]
__device__ float  g_PP [KC * B_ * NCHUNK * N_];   // chunk decay prod   [ch][s][n]
__device__ int    g_FLAG[NCHUNK * NBX];           // look-back flags

// ---------------- kernel 1: transpose x -> xT (+ zero flags) -----------------
__global__ void k_transpose(const float* __restrict__ x) {
    if (blockIdx.x == 0)
        for (int i = threadIdx.x; i < NCHUNK * NBX; i += blockDim.x)
            g_FLAG[i] = 0;
    int bc = blockIdx.x;
    __shared__ float s[L_];
    float4* s4 = reinterpret_cast<float4*>(s);
    const float4* src = reinterpret_cast<const float4*>(x + (size_t)bc * L_);
    for (int i = threadIdx.x; i < L_ / 4; i += blockDim.x) s4[i] = src[i];
    __syncthreads();
    float4* dst = reinterpret_cast<float4*>(g_xT + (size_t)bc * L_);
    for (int i = threadIdx.x; i < L_ / 4; i += blockDim.x) {
        int p = 4 * i;                 // dst index j = w*Hh + h
        int w = p / Hh, h = p % Hh;    // 4 consecutive j -> same w, h..h+3
        dst[i] = make_float4(s[(h + 0) * Ww + w], s[(h + 1) * Ww + w],
                             s[(h + 2) * Ww + w], s[(h + 3) * Ww + w]);
    }
}

// ---------------- kernel 2: proj GEMM + BC repack + dt-proj + softplus --------
// P-tile = 32 positions. grid (72, 1, 4).
__global__ __launch_bounds__(256) void k_proj(
    const float* __restrict__ x,
    const float* __restrict__ Wp,        // [K*44][192]
    const float* __restrict__ dtw,       // [K][C][R]
    const float* __restrict__ dt_bias)   // [K*C]
{
    int bs = blockIdx.z;            // b*2 + s
    int b  = bs >> 1, s = bs & 1;
    int p0 = blockIdx.x * 32;

    const float* X = (s ? g_xT : x) + (size_t)b * C_ * L_;

    __shared__ float Ws[16][96];        // [kk][m]
    __shared__ float Xs[16][32];        // [kk][pp]
    __shared__ float dtw2[2][C_ * R_];  // per k-part, [c*12 + r]
    __shared__ float dts2[2][R_][32];   // staged dt rows

    int tid = threadIdx.x;
    int tx = tid & 15, ty = tid >> 4;

    // load dt weights for both k-parts (k = s, s+2)
    for (int part = 0; part < 2; part++) {
        int k = s + 2 * part;
        for (int idx = tid; idx < C_ * R_; idx += 256)
            dtw2[part][idx] = dtw[(size_t)k * C_ * R_ + idx];
    }

    float acc[6][2];
#pragma unroll
    for (int i = 0; i < 6; i++) { acc[i][0] = 0.f; acc[i][1] = 0.f; }

    for (int c0 = 0; c0 < C_; c0 += 16) {
        for (int idx = tid; idx < 96 * 16; idx += 256) {
            int m = idx >> 4, kk = idx & 15;
            float v = 0.f;
            if (m < 88) {
                int k = s + (m < D44 ? 0 : 2);
                int d = (m < D44) ? m : (m - D44);
                v = Wp[(size_t)(k * D44 + d) * C_ + c0 + kk];
            }
            Ws[kk][m] = v;
        }
        for (int idx = tid; idx < 16 * 32; idx += 256) {
            int c = idx >> 5, pp = idx & 31;
            Xs[c][pp] = X[(size_t)(c0 + c) * L_ + p0 + pp];
        }
        __syncthreads();
#pragma unroll
        for (int kk = 0; kk < 16; kk++) {
            float xa0 = Xs[kk][tx], xa1 = Xs[kk][tx + 16];
            float wa[6];
#pragma unroll
            for (int i = 0; i < 6; i++) wa[i] = Ws[kk][ty + 16 * i];
#pragma unroll
            for (int i = 0; i < 6; i++) {
                acc[i][0] = fmaf(wa[i], xa0, acc[i][0]);
                acc[i][1] = fmaf(wa[i], xa1, acc[i][1]);
            }
        }
        __syncthreads();
    }

    // epilogue: dt rows -> smem; B/C rows -> fp16 global layout
#pragma unroll
    for (int i = 0; i < 6; i++) {
        int m = ty + 16 * i;
        if (m < 88) {
            int part = (m < D44) ? 0 : 1;
            int d = m - part * D44;
            int k = s + 2 * part;
            if (d < R_) {
                dts2[part][d][tx]      = acc[i][0];
                dts2[part][d][tx + 16] = acc[i][1];
            } else {
                int jbc = d - R_;
                int n = jbc & 15, isC = jbc >> 4;
                __half* base = g_BC + (size_t)(b * K_ + k) * (L_ / 16) * 512;
#pragma unroll
                for (int j = 0; j < 2; j++) {
                    int p = p0 + tx + 16 * j;
                    int g = p >> 4, t = (p >> 2) & 3, e = p & 3;
                    base[(size_t)g * 512 + isC * 256 + t * 64 + n * 4 + e] =
                        __float2half(acc[i][j]);
                }
            }
        }
    }
    __syncthreads();

    // dt projection + softplus for both k-parts: 2 * 192 * 32 outputs
    for (int idx = tid; idx < 2 * C_ * 32; idx += 256) {
        int part = idx / (C_ * 32);
        int rem  = idx - part * (C_ * 32);
        int c = rem >> 5, p = rem & 31;
        int k = s + 2 * part;
        float accv = dt_bias[k * C_ + c];
        const float* wr = &dtw2[part][c * R_];
#pragma unroll
        for (int r = 0; r < R_; r++)
            accv = fmaf(wr[r], dts2[part][r][p], accv);
        float sp = (accv > 20.f) ? accv : log1pf(__expf(accv));
        g_SP[(size_t)((b * K_ + k) * C_ + c) * L_ + p0 + p] = sp;
    }
}

// half4 load helper: one LDG.64, expand to 4 floats
__device__ __forceinline__ void ld_half4(const __half* p, float* out) {
    uint2 raw = *reinterpret_cast<const uint2*>(p);
    __half2 h0 = *reinterpret_cast<__half2*>(&raw.x);
    __half2 h1 = *reinterpret_cast<__half2*>(&raw.y);
    float2 f0 = __half22float2(h0), f1 = __half22float2(h1);
    out[0] = f0.x; out[1] = f0.y; out[2] = f1.x; out[3] = f1.y;
}

// ---------------- scan phase A body: chunk-local (h_end, P), 8-pos batches ----
template<bool FWD>
__device__ __forceinline__ void scan_pA(
    const float* __restrict__ sp, const float* __restrict__ u,
    const __half* __restrict__ bc, float a2, int n, int g0,
    float& h, float& P)
{
    h = 0.f;
    float ssum = 0.f;
    for (int g = g0; g < g0 + BPC; g++) {
        int q = FWD ? 8 * g : (L_ - 8 - 8 * g);
        const __half* rec = bc + (size_t)(q >> 4) * 512 + ((q >> 2) & 3) * 64 + n * 4;
        float spArr[8], uArr[8], Bl[8];
#pragma unroll
        for (int t = 0; t < 2; t++) {
            float4 s4 = *reinterpret_cast<const float4*>(sp + q + 4 * t);
            float4 u4 = *reinterpret_cast<const float4*>(u  + q + 4 * t);
            ld_half4(rec + t * 64, Bl + 4 * t);
            spArr[4*t+0]=s4.x; spArr[4*t+1]=s4.y; spArr[4*t+2]=s4.z; spArr[4*t+3]=s4.w;
            uArr [4*t+0]=u4.x; uArr [4*t+1]=u4.y; uArr [4*t+2]=u4.z; uArr [4*t+3]=u4.w;
        }
        float dA[8], dBu[8];
#pragma unroll
        for (int j = 0; j < 8; j++) {
            int mj = FWD ? j : 7 - j;
            float s_ = spArr[mj];
            ssum += s_;
            dA[j]  = exp2f(s_ * a2);
            dBu[j] = s_ * uArr[mj] * Bl[mj];
        }
#pragma unroll
        for (int j = 0; j < 8; j++)
            h = fmaf(dA[j], h, dBu[j]);
    }
    P = exp2f(a2 * ssum);
}

// ---------------- scan phase B body: full scan + reduction, 8-pos batches -----
template<bool FWD>
__device__ __forceinline__ void scan_pB(
    const float* __restrict__ sp, const float* __restrict__ u,
    const __half* __restrict__ bc, float* __restrict__ y,
    float a2, float Dv, int n, int g0, float h)
{
    const unsigned FULL = 0xffffffffu;
    const bool hi8 = (n & 8), hi4 = (n & 4), hi2 = (n & 2);
    int jmine = (n >> 1) & 7;                     // position this lane reports
    bool writer = !(n & 1);

    for (int g = g0; g < g0 + BPC; g++) {
        int q = FWD ? 8 * g : (L_ - 8 - 8 * g);
        const __half* rec = bc + (size_t)(q >> 4) * 512 + ((q >> 2) & 3) * 64 + n * 4;

        float spArr[8], uArr[8], Bl[8], Cl[8];
#pragma unroll
        for (int t = 0; t < 2; t++) {
            float4 s4 = *reinterpret_cast<const float4*>(sp + q + 4 * t);
            float4 u4 = *reinterpret_cast<const float4*>(u  + q + 4 * t);
            ld_half4(rec + t * 64, Bl + 4 * t);
            ld_half4(rec + 256 + t * 64, Cl + 4 * t);
            spArr[4*t+0]=s4.x; spArr[4*t+1]=s4.y; spArr[4*t+2]=s4.z; spArr[4*t+3]=s4.w;
            uArr [4*t+0]=u4.x; uArr [4*t+1]=u4.y; uArr [4*t+2]=u4.z; uArr [4*t+3]=u4.w;
        }

        float dA[8], dBu[8];
#pragma unroll
        for (int j = 0; j < 8; j++) {
            int mj = FWD ? j : 7 - j;
            float s_ = spArr[mj];
            dA[j]  = exp2f(s_ * a2);
            dBu[j] = s_ * uArr[mj] * Bl[mj];
        }

        float yp[8];
#pragma unroll
        for (int j = 0; j < 8; j++) {
            int mj = FWD ? j : 7 - j;
            h = fmaf(dA[j], h, dBu[j]);
            yp[j] = h * Cl[mj];
        }

        // multi-reduce: 8 positions over 16 lanes; j2->bit3, j1->bit2, j0->bit1
        float w4[4];
#pragma unroll
        for (int t = 0; t < 4; t++) {
            float keepv = hi8 ? yp[t + 4] : yp[t];
            float sendv = hi8 ? yp[t] : yp[t + 4];
            w4[t] = keepv + __shfl_xor_sync(FULL, sendv, 8);
        }
        float w2[2];
#pragma unroll
        for (int t = 0; t < 2; t++) {
            float keepv = hi4 ? w4[t + 2] : w4[t];
            float sendv = hi4 ? w4[t] : w4[t + 2];
            w2[t] = keepv + __shfl_xor_sync(FULL, sendv, 4);
        }
        float w1;
        {
            float keepv = hi2 ? w2[1] : w2[0];
            float sendv = hi2 ? w2[0] : w2[1];
            w1 = keepv + __shfl_xor_sync(FULL, sendv, 2);
        }
        {
            float yred = w1 + __shfl_xor_sync(FULL, w1, 1);
            int p = q + (FWD ? jmine : 7 - jmine);
            if (writer)
                y[p] = fmaf(Dv, u[p], yred);
        }
    }
}

// ---------------- fused single-pass scan with decoupled look-back -------------
__global__ __launch_bounds__(128, 9) void k_scanf(
    const float* __restrict__ x,
    const float* __restrict__ A_logs,
    const float* __restrict__ Ds)
{
    int warpId = threadIdx.x >> 5;          // 0..3
    int lane = threadIdx.x & 31;
    int bx = blockIdx.x;
    int gw = bx * 4 + warpId;               // 0..767
    int s = blockIdx.y;                      // chunk (scan-time)
    int half = lane >> 4, n = lane & 15;
    int ch = gw * 2 + half;                  // 0..1535
    int c = ch % C_;
    int k = (ch / C_) & 3;
    int b = ch / (K_ * C_);
    int kc = k * C_ + c;

    float a2 = -LOG2E * __expf(A_logs[kc * N_ + n]);
    float Dv = Ds[kc];

    const float* sp = g_SP + (size_t)ch * L_;
    const float* u  = ((k & 1) ? g_xT : x) + (size_t)(b * C_ + c) * L_;
    const __half* bc = g_BC + (size_t)(b * K_ + k) * (L_ / 16) * 512;
    float* y        = g_Y + (size_t)ch * L_;

    bool fwd = (k < 2);

    // ---- phase A: local (h,P); skipped for last chunk (unused) ----
    if (s < NCHUNK - 1) {
        float h, P;
        if (fwd) scan_pA<true >(sp, u, bc, a2, n, s * BPC, h, P);
        else     scan_pA<false>(sp, u, bc, a2, n, s * BPC, h, P);
        size_t o = ((size_t)ch * NCHUNK + s) * N_ + n;
        g_HP[o] = h;
        g_PP[o] = P;
        __syncthreads();
        if (threadIdx.x == 0) {
            __threadfence();
            atomicExch(&g_FLAG[s * NBX + bx], 1);
        }
    }

    // ---- look-back: wait for all predecessor chunks, fold h0 ----
    float h0 = 0.f;
    if (s > 0) {
        if (threadIdx.x < s) {
            while (atomicAdd(&g_FLAG[threadIdx.x * NBX + bx], 0) == 0)
                __nanosleep(64);
            __threadfence();
        }
        __syncthreads();

        float Pv[NCHUNK - 1], Hv[NCHUNK - 1];
#pragma unroll
        for (int s2 = 0; s2 < NCHUNK - 1; s2++) {
            size_t o = ((size_t)ch * NCHUNK + s2) * N_ + n;
            bool act = (s2 < s);
            Pv[s2] = act ? __ldcg(&g_PP[o]) : 1.f;
            Hv[s2] = act ? __ldcg(&g_HP[o]) : 0.f;
        }
#pragma unroll
        for (int s2 = 0; s2 < NCHUNK - 1; s2++)
            h0 = fmaf(Pv[s2], h0, Hv[s2]);
    }

    // ---- phase B: full scan with corrected h0 ----
    if (fwd) scan_pB<true >(sp, u, bc, y, a2, Dv, n, s * BPC, h0);
    else     scan_pB<false>(sp, u, bc, y, a2, Dv, n, s * BPC, h0);
}

// ---------------- kernel 4: cross merge (vectorized, full-MLP) ----------------
__global__ __launch_bounds__(256) void k_merge(float* __restrict__ out) {
    int bc = blockIdx.x;
    int b = bc / C_, c = bc % C_;
    const float4* y0 = reinterpret_cast<const float4*>(g_Y + (size_t)((b * K_ + 0) * C_ + c) * L_);
    const float4* y1 = reinterpret_cast<const float4*>(g_Y + (size_t)((b * K_ + 1) * C_ + c) * L_);
    const float4* y2 = reinterpret_cast<const float4*>(g_Y + (size_t)((b * K_ + 2) * C_ + c) * L_);
    const float4* y3 = reinterpret_cast<const float4*>(g_Y + (size_t)((b * K_ + 3) * C_ + c) * L_);
    __shared__ float s1[L_];
    float4* s1v = reinterpret_cast<float4*>(s1);

    int tid = threadIdx.x;
    float4 r02[3];
#pragma unroll
    for (int t = 0; t < 3; t++) {
        int i = tid + 256 * t;
        if (i < L_ / 4) {
            float4 a = y1[i], bb = y3[i];
            s1v[i] = make_float4(a.x + bb.x, a.y + bb.y, a.z + bb.z, a.w + bb.w);
            float4 p = y0[i], q = y2[i];
            r02[t] = make_float4(p.x + q.x, p.y + q.y, p.z + q.z, p.w + q.w);
        }
    }
    __syncthreads();

    float4* o4 = reinterpret_cast<float4*>(out + (size_t)bc * L_);
#pragma unroll
    for (int t = 0; t < 3; t++) {
        int i = tid + 256 * t;
        if (i < L_ / 4) {
            int p = 4 * i;               // out index j = h*Ww + w
            int h = p / Ww, w = p % Ww;  // 4 consecutive j -> same h, w..w+3
            float4 v = r02[t];
            v.x += s1[(w + 0) * Hh + h];
            v.y += s1[(w + 1) * Hh + h];
            v.z += s1[(w + 2) * Hh + h];
            v.w += s1[(w + 3) * Hh + h];
            o4[i] = v;
        }
    }
}

// ---------------- launch -------------------------------------------------------
extern "C" void kernel_launch(void* const* d_in, const int* in_sizes, int n_in,
                              void* d_out, int out_size) {
    const float* x       = (const float*)d_in[0];
    const float* xpw     = (const float*)d_in[1];
    const float* dtw     = (const float*)d_in[2];
    const float* A_logs  = (const float*)d_in[3];
    const float* Ds      = (const float*)d_in[4];
    const float* dt_bias = (const float*)d_in[5];
    float* out = (float*)d_out;

    k_transpose<<<B_ * C_, 256>>>(x);

    {
        dim3 grid(L_ / 32, 1, 4);
        k_proj<<<grid, 256>>>(x, xpw, dtw, dt_bias);
    }
    {
        dim3 grid(NBX, NCHUNK);
        k_scanf<<<grid, 128>>>(x, A_logs, Ds);
    }
    k_merge<<<B_ * C_, 256>>>(out);
}

// round 14
// speedup vs baseline: 1.0338x; 1.0311x over previous
#include <cuda_runtime.h>
#include <cuda_bf16.h>
#include <cuda_fp16.h>
#include <math.h>

// Problem constants
#define B_  2
#define C_  192       // DINNER
#define Hh  48
#define Ww  48
#define L_  2304      // H*W
#define K_  4
#define N_  16
#define R_  12
#define D44 44        // R + 2N
#define KC  (K_*C_)   // 768

#define NCHUNK 16
#define GPC    9      // 16-position groups per chunk (chunk = 144)
#define NBX    192    // blocks per chunk (x-dim), 4 warps each
#define LOG2E  1.4426950408889634f

// BC layout (fp16): per (b,k), per 16-position record g:
//   B block: [t:4][n:16][4 halfs] (512B) then C block likewise (512B)
// record stride = 512 halfs.

// ---------------- scratch (device globals; no allocation allowed) ------------
__device__ float  g_xT[B_ * C_ * L_];
__device__ __half g_BC[B_ * K_ * (L_ / 16) * 512];
__device__ float  g_SP[B_ * K_ * C_ * L_];
__device__ float  g_Y [B_ * K_ * C_ * L_];
__device__ float  g_HP [KC * B_ * NCHUNK * N_];   // chunk-local h_end  [ch][s][n]
__device__ float  g_PP [KC * B_ * NCHUNK * N_];   // chunk decay prod   [ch][s][n]
__device__ int    g_FLAG[NCHUNK * NBX];           // look-back flags

// ---------------- kernel 1: transpose x -> xT (+ zero flags) -----------------
__global__ void k_transpose(const float* __restrict__ x) {
    if (blockIdx.x == 0)
        for (int i = threadIdx.x; i < NCHUNK * NBX; i += blockDim.x)
            g_FLAG[i] = 0;
    int bc = blockIdx.x;
    __shared__ float s[L_];
    float4* s4 = reinterpret_cast<float4*>(s);
    const float4* src = reinterpret_cast<const float4*>(x + (size_t)bc * L_);
    for (int i = threadIdx.x; i < L_ / 4; i += blockDim.x) s4[i] = src[i];
    __syncthreads();
    float4* dst = reinterpret_cast<float4*>(g_xT + (size_t)bc * L_);
    for (int i = threadIdx.x; i < L_ / 4; i += blockDim.x) {
        int p = 4 * i;                 // dst index j = w*Hh + h
        int w = p / Hh, h = p % Hh;    // 4 consecutive j -> same w, h..h+3
        dst[i] = make_float4(s[(h + 0) * Ww + w], s[(h + 1) * Ww + w],
                             s[(h + 2) * Ww + w], s[(h + 3) * Ww + w]);
    }
}

// ---------------- kernel 2: proj GEMM + BC repack + dt-proj + softplus --------
// P-tile = 32 positions. grid (72, 1, 4).
__global__ __launch_bounds__(256) void k_proj(
    const float* __restrict__ x,
    const float* __restrict__ Wp,        // [K*44][192]
    const float* __restrict__ dtw,       // [K][C][R]
    const float* __restrict__ dt_bias)   // [K*C]
{
    int bs = blockIdx.z;            // b*2 + s
    int b  = bs >> 1, s = bs & 1;
    int p0 = blockIdx.x * 32;

    const float* X = (s ? g_xT : x) + (size_t)b * C_ * L_;

    __shared__ float Ws[16][96];        // [kk][m]
    __shared__ float Xs[16][32];        // [kk][pp]
    __shared__ float dtw2[2][C_ * R_];  // per k-part, [c*12 + r]
    __shared__ float dts2[2][R_][32];   // staged dt rows

    int tid = threadIdx.x;
    int tx = tid & 15, ty = tid >> 4;

    // load dt weights for both k-parts (k = s, s+2)
    for (int part = 0; part < 2; part++) {
        int k = s + 2 * part;
        for (int idx = tid; idx < C_ * R_; idx += 256)
            dtw2[part][idx] = dtw[(size_t)k * C_ * R_ + idx];
    }

    float acc[6][2];
#pragma unroll
    for (int i = 0; i < 6; i++) { acc[i][0] = 0.f; acc[i][1] = 0.f; }

    for (int c0 = 0; c0 < C_; c0 += 16) {
        for (int idx = tid; idx < 96 * 16; idx += 256) {
            int m = idx >> 4, kk = idx & 15;
            float v = 0.f;
            if (m < 88) {
                int k = s + (m < D44 ? 0 : 2);
                int d = (m < D44) ? m : (m - D44);
                v = Wp[(size_t)(k * D44 + d) * C_ + c0 + kk];
            }
            Ws[kk][m] = v;
        }
        for (int idx = tid; idx < 16 * 32; idx += 256) {
            int c = idx >> 5, pp = idx & 31;
            Xs[c][pp] = X[(size_t)(c0 + c) * L_ + p0 + pp];
        }
        __syncthreads();
#pragma unroll
        for (int kk = 0; kk < 16; kk++) {
            float xa0 = Xs[kk][tx], xa1 = Xs[kk][tx + 16];
            float wa[6];
#pragma unroll
            for (int i = 0; i < 6; i++) wa[i] = Ws[kk][ty + 16 * i];
#pragma unroll
            for (int i = 0; i < 6; i++) {
                acc[i][0] = fmaf(wa[i], xa0, acc[i][0]);
                acc[i][1] = fmaf(wa[i], xa1, acc[i][1]);
            }
        }
        __syncthreads();
    }

    // epilogue: dt rows -> smem; B/C rows -> fp16 global layout
#pragma unroll
    for (int i = 0; i < 6; i++) {
        int m = ty + 16 * i;
        if (m < 88) {
            int part = (m < D44) ? 0 : 1;
            int d = m - part * D44;
            int k = s + 2 * part;
            if (d < R_) {
                dts2[part][d][tx]      = acc[i][0];
                dts2[part][d][tx + 16] = acc[i][1];
            } else {
                int jbc = d - R_;
                int n = jbc & 15, isC = jbc >> 4;
                __half* base = g_BC + (size_t)(b * K_ + k) * (L_ / 16) * 512;
#pragma unroll
                for (int j = 0; j < 2; j++) {
                    int p = p0 + tx + 16 * j;
                    int g = p >> 4, t = (p >> 2) & 3, e = p & 3;
                    base[(size_t)g * 512 + isC * 256 + t * 64 + n * 4 + e] =
                        __float2half(acc[i][j]);
                }
            }
        }
    }
    __syncthreads();

    // dt projection + softplus for both k-parts: 2 * 192 * 32 outputs
    for (int idx = tid; idx < 2 * C_ * 32; idx += 256) {
        int part = idx / (C_ * 32);
        int rem  = idx - part * (C_ * 32);
        int c = rem >> 5, p = rem & 31;
        int k = s + 2 * part;
        float accv = dt_bias[k * C_ + c];
        const float* wr = &dtw2[part][c * R_];
#pragma unroll
        for (int r = 0; r < R_; r++)
            accv = fmaf(wr[r], dts2[part][r][p], accv);
        float sp = (accv > 20.f) ? accv : log1pf(__expf(accv));
        g_SP[(size_t)((b * K_ + k) * C_ + c) * L_ + p0 + p] = sp;
    }
}

// half4 load helper: one 8B load, expand to 4 floats (works for global or shared)
__device__ __forceinline__ void ld_half4(const __half* p, float* out) {
    uint2 raw = *reinterpret_cast<const uint2*>(p);
    __half2 h0 = *reinterpret_cast<__half2*>(&raw.x);
    __half2 h1 = *reinterpret_cast<__half2*>(&raw.y);
    float2 f0 = __half22float2(h0), f1 = __half22float2(h1);
    out[0] = f0.x; out[1] = f0.y; out[2] = f1.x; out[3] = f1.y;
}

// ---------------- scan phase A body: chunk-local (h_end, P) -------------------
// sbc: shared-memory copy of this chunk's BC records (base_rec .. base_rec+GPC)
template<bool FWD>
__device__ __forceinline__ void scan_pA(
    const float* __restrict__ sp, const float* __restrict__ u,
    const __half* sbc, int base_rec, float a2, int n, int g0,
    float& h, float& P)
{
    h = 0.f;
    float ssum = 0.f;
    for (int g = g0; g < g0 + GPC; g++) {
        int q = FWD ? 16 * g : (L_ - 16 - 16 * g);
        const __half* rec = sbc + ((q >> 4) - base_rec) * 512 + n * 4;
        float spArr[16], uArr[16], Bl[16];
#pragma unroll
        for (int t = 0; t < 4; t++) {
            float4 s4 = *reinterpret_cast<const float4*>(sp + q + 4 * t);
            float4 u4 = *reinterpret_cast<const float4*>(u  + q + 4 * t);
            ld_half4(rec + t * 64, Bl + 4 * t);
            spArr[4*t+0]=s4.x; spArr[4*t+1]=s4.y; spArr[4*t+2]=s4.z; spArr[4*t+3]=s4.w;
            uArr [4*t+0]=u4.x; uArr [4*t+1]=u4.y; uArr [4*t+2]=u4.z; uArr [4*t+3]=u4.w;
        }
        float dA[16], dBu[16];
#pragma unroll
        for (int j = 0; j < 16; j++) {
            int mj = FWD ? j : 15 - j;
            float s_ = spArr[mj];
            ssum += s_;
            dA[j]  = exp2f(s_ * a2);
            dBu[j] = s_ * uArr[mj] * Bl[mj];
        }
#pragma unroll
        for (int j = 0; j < 16; j++)
            h = fmaf(dA[j], h, dBu[j]);
    }
    P = exp2f(a2 * ssum);
}

// ---------------- scan phase B body: full scan + reduction --------------------
template<bool FWD>
__device__ __forceinline__ void scan_pB(
    const float* __restrict__ sp, const float* __restrict__ u,
    const __half* sbc, int base_rec, float* __restrict__ y,
    float a2, float Dv, int n, int g0, float h)
{
    const unsigned FULL = 0xffffffffu;
    const bool hi8 = (n & 8), hi4 = (n & 4), hi2 = (n & 2), hi1 = (n & 1);

    for (int g = g0; g < g0 + GPC; g++) {
        int q = FWD ? 16 * g : (L_ - 16 - 16 * g);
        const __half* rec = sbc + ((q >> 4) - base_rec) * 512 + n * 4;

        float spArr[16], uArr[16], Bl[16], Cl[16];
#pragma unroll
        for (int t = 0; t < 4; t++) {
            float4 s4 = *reinterpret_cast<const float4*>(sp + q + 4 * t);
            float4 u4 = *reinterpret_cast<const float4*>(u  + q + 4 * t);
            ld_half4(rec + t * 64, Bl + 4 * t);
            ld_half4(rec + 256 + t * 64, Cl + 4 * t);
            spArr[4*t+0]=s4.x; spArr[4*t+1]=s4.y; spArr[4*t+2]=s4.z; spArr[4*t+3]=s4.w;
            uArr [4*t+0]=u4.x; uArr [4*t+1]=u4.y; uArr [4*t+2]=u4.z; uArr [4*t+3]=u4.w;
        }

        float dA[16], dBu[16];
#pragma unroll
        for (int j = 0; j < 16; j++) {
            int mj = FWD ? j : 15 - j;
            float s_ = spArr[mj];
            dA[j]  = exp2f(s_ * a2);
            dBu[j] = s_ * uArr[mj] * Bl[mj];
        }

        float yp[16];
#pragma unroll
        for (int j = 0; j < 16; j++) {
            int mj = FWD ? j : 15 - j;
            h = fmaf(dA[j], h, dBu[j]);
            yp[j] = h * Cl[mj];
        }

        float w8[8];
#pragma unroll
        for (int t = 0; t < 8; t++) {
            float keepv = hi8 ? yp[t + 8] : yp[t];
            float sendv = hi8 ? yp[t] : yp[t + 8];
            w8[t] = keepv + __shfl_xor_sync(FULL, sendv, 8);
        }
        float w4[4];
#pragma unroll
        for (int t = 0; t < 4; t++) {
            float keepv = hi4 ? w8[t + 4] : w8[t];
            float sendv = hi4 ? w8[t] : w8[t + 4];
            w4[t] = keepv + __shfl_xor_sync(FULL, sendv, 4);
        }
        float w2[2];
#pragma unroll
        for (int t = 0; t < 2; t++) {
            float keepv = hi2 ? w4[t + 2] : w4[t];
            float sendv = hi2 ? w4[t] : w4[t + 2];
            w2[t] = keepv + __shfl_xor_sync(FULL, sendv, 2);
        }
        {
            float keepv = hi1 ? w2[1] : w2[0];
            float sendv = hi1 ? w2[0] : w2[1];
            float yred = keepv + __shfl_xor_sync(FULL, sendv, 1);
            int p = q + (FWD ? n : 15 - n);
            y[p] = fmaf(Dv, u[p], yred);
        }
    }
}

// ---------------- fused single-pass scan with decoupled look-back -------------
__global__ __launch_bounds__(128) void k_scanf(
    const float* __restrict__ x,
    const float* __restrict__ A_logs,
    const float* __restrict__ Ds)
{
    __shared__ __half s_bc[GPC * 512];      // this chunk's BC records (9.2 KB)

    int warpId = threadIdx.x >> 5;          // 0..3
    int lane = threadIdx.x & 31;
    int bx = blockIdx.x;
    int gw = bx * 4 + warpId;               // 0..767
    int s = blockIdx.y;                      // chunk (scan-time)
    int half = lane >> 4, n = lane & 15;
    int ch = gw * 2 + half;                  // 0..1535
    int c = ch % C_;
    int k = (ch / C_) & 3;
    int b = ch / (K_ * C_);
    int kc = k * C_ + c;

    float a2 = -LOG2E * __expf(A_logs[kc * N_ + n]);
    float Dv = Ds[kc];

    const float* sp = g_SP + (size_t)ch * L_;
    const float* u  = ((k & 1) ? g_xT : x) + (size_t)(b * C_ + c) * L_;
    const __half* bc = g_BC + (size_t)(b * K_ + k) * (L_ / 16) * 512;
    float* y        = g_Y + (size_t)ch * L_;

    bool fwd = (k < 2);
    // all 8 channels of this block share (b,k) -> shared BC records.
    int base_rec = fwd ? s * GPC : (L_ / 16 - (s + 1) * GPC);

    // cooperative fill of this chunk's BC records into shared
    {
        const float4* src = reinterpret_cast<const float4*>(bc + (size_t)base_rec * 512);
        float4* dst = reinterpret_cast<float4*>(s_bc);
        for (int i = threadIdx.x; i < GPC * 512 / 8; i += 128)
            dst[i] = src[i];
    }
    __syncthreads();

    // ---- phase A: local (h,P); skipped for last chunk (unused) ----
    if (s < NCHUNK - 1) {
        float h, P;
        if (fwd) scan_pA<true >(sp, u, s_bc, base_rec, a2, n, s * GPC, h, P);
        else     scan_pA<false>(sp, u, s_bc, base_rec, a2, n, s * GPC, h, P);
        size_t o = ((size_t)ch * NCHUNK + s) * N_ + n;
        g_HP[o] = h;
        g_PP[o] = P;
        __syncthreads();
        if (threadIdx.x == 0) {
            __threadfence();
            atomicExch(&g_FLAG[s * NBX + bx], 1);
        }
    }

    // ---- look-back: wait for all predecessor chunks, fold h0 ----
    float h0 = 0.f;
    if (s > 0) {
        if (threadIdx.x < s) {
            while (atomicAdd(&g_FLAG[threadIdx.x * NBX + bx], 0) == 0)
                __nanosleep(64);
            __threadfence();
        }
        __syncthreads();

        float Pv[NCHUNK - 1], Hv[NCHUNK - 1];
#pragma unroll
        for (int s2 = 0; s2 < NCHUNK - 1; s2++) {
            size_t o = ((size_t)ch * NCHUNK + s2) * N_ + n;
            bool act = (s2 < s);
            Pv[s2] = act ? __ldcg(&g_PP[o]) : 1.f;
            Hv[s2] = act ? __ldcg(&g_HP[o]) : 0.f;
        }
#pragma unroll
        for (int s2 = 0; s2 < NCHUNK - 1; s2++)
            h0 = fmaf(Pv[s2], h0, Hv[s2]);
    }

    // ---- phase B: full scan with corrected h0 ----
    if (fwd) scan_pB<true >(sp, u, s_bc, base_rec, y, a2, Dv, n, s * GPC, h0);
    else     scan_pB<false>(sp, u, s_bc, base_rec, y, a2, Dv, n, s * GPC, h0);
}

// ---------------- kernel 4: cross merge (vectorized, full-MLP) ----------------
__global__ __launch_bounds__(256) void k_merge(float* __restrict__ out) {
    int bc = blockIdx.x;
    int b = bc / C_, c = bc % C_;
    const float4* y0 = reinterpret_cast<const float4*>(g_Y + (size_t)((b * K_ + 0) * C_ + c) * L_);
    const float4* y1 = reinterpret_cast<const float4*>(g_Y + (size_t)((b * K_ + 1) * C_ + c) * L_);
    const float4* y2 = reinterpret_cast<const float4*>(g_Y + (size_t)((b * K_ + 2) * C_ + c) * L_);
    const float4* y3 = reinterpret_cast<const float4*>(g_Y + (size_t)((b * K_ + 3) * C_ + c) * L_);
    __shared__ float s1[L_];
    float4* s1v = reinterpret_cast<float4*>(s1);

    int tid = threadIdx.x;
    float4 r02[3];
#pragma unroll
    for (int t = 0; t < 3; t++) {
        int i = tid + 256 * t;
        if (i < L_ / 4) {
            float4 a = y1[i], bb = y3[i];
            s1v[i] = make_float4(a.x + bb.x, a.y + bb.y, a.z + bb.z, a.w + bb.w);
            float4 p = y0[i], q = y2[i];
            r02[t] = make_float4(p.x + q.x, p.y + q.y, p.z + q.z, p.w + q.w);
        }
    }
    __syncthreads();

    float4* o4 = reinterpret_cast<float4*>(out + (size_t)bc * L_);
#pragma unroll
    for (int t = 0; t < 3; t++) {
        int i = tid + 256 * t;
        if (i < L_ / 4) {
            int p = 4 * i;               // out index j = h*Ww + w
            int h = p / Ww, w = p % Ww;  // 4 consecutive j -> same h, w..w+3
            float4 v = r02[t];
            v.x += s1[(w + 0) * Hh + h];
            v.y += s1[(w + 1) * Hh + h];
            v.z += s1[(w + 2) * Hh + h];
            v.w += s1[(w + 3) * Hh + h];
            o4[i] = v;
        }
    }
}

// ---------------- launch -------------------------------------------------------
extern "C" void kernel_launch(void* const* d_in, const int* in_sizes, int n_in,
                              void* d_out, int out_size) {
    const float* x       = (const float*)d_in[0];
    const float* xpw     = (const float*)d_in[1];
    const float* dtw     = (const float*)d_in[2];
    const float* A_logs  = (const float*)d_in[3];
    const float* Ds      = (const float*)d_in[4];
    const float* dt_bias = (const float*)d_in[5];
    float* out = (float*)d_out;

    k_transpose<<<B_ * C_, 256>>>(x);

    {
        dim3 grid(L_ / 32, 1, 4);
        k_proj<<<grid, 256>>>(x, xpw, dtw, dt_bias);
    }
    {
        dim3 grid(NBX, NCHUNK);
        k_scanf<<<grid, 128>>>(x, A_logs, Ds);
    }
    k_merge<<<B_ * C_, 256>>>(out);
}